// round 14
// baseline (speedup 1.0000x reference)
#include <cuda_runtime.h>
#include <cuda_fp16.h>
#include <cuda_bf16.h>

#define N_NODES 100000
#define N_EDGES 3200000
#define IN_CH   128
#define HID     16
#define MAXD    64            // fixed adjacency stride; overflow handled exactly
#define OVF_MAX 4096
#define NBUCKET 128

// ---------------- device scratch (no allocation allowed) ----------------
__device__ __align__(16) int    g_cnt[N_NODES];
__device__ __align__(16) int    g_adj[N_NODES * MAXD];   // 25.6 MB fixed-stride adjacency
__device__ int                  g_ovf_cnt;
__device__ __align__(16) int    g_ovf[2 * OVF_MAX];      // (col,row) overflow pairs
__device__ __align__(16) int    g_bkt [NBUCKET];         // degree histogram
__device__ __align__(16) int    g_bcur[NBUCKET];         // bucket fill cursors
__device__ __align__(16) int    g_perm[N_NODES];         // degree-sorted node order
__device__ __align__(16) __half g_hs [N_NODES * HID];    // layer-1 messages (fp16)
__device__ __align__(16) __half g_hs2[N_NODES * HID];    // layer-2 messages (fp16)

__device__ __forceinline__ unsigned h2u(__half2 h) {
    return *reinterpret_cast<unsigned*>(&h);
}

// ---------------- build ----------------

__global__ void k_zero(int n4) {
    int i = blockIdx.x * blockDim.x + threadIdx.x;
    if (i < n4) ((int4*)g_cnt)[i] = make_int4(0, 0, 0, 0);
    if (i < NBUCKET / 4) ((int4*)g_bkt)[i] = make_int4(0, 0, 0, 0);
    if (i == 0) g_ovf_cnt = 0;
}

// single-pass adjacency build; atomic return value doubles as degree histogram
__global__ void k_build(const int* __restrict__ row, const int* __restrict__ col, int e4) {
    int i = blockIdx.x * blockDim.x + threadIdx.x;
    if (i >= e4) return;
    int4 r = __ldg(&((const int4*)row)[i]);
    int4 c = __ldg(&((const int4*)col)[i]);
#pragma unroll
    for (int u = 0; u < 4; u++) {
        int cc = (u == 0) ? c.x : (u == 1) ? c.y : (u == 2) ? c.z : c.w;
        int rr = (u == 0) ? r.x : (u == 1) ? r.y : (u == 2) ? r.z : r.w;
        int p = atomicAdd(&g_cnt[cc], 1);
        if (p < MAXD) {
            g_adj[(cc << 6) + p] = rr;
        } else {
            int o = atomicAdd(&g_ovf_cnt, 1);
            if (o < OVF_MAX) { g_ovf[2 * o] = cc; g_ovf[2 * o + 1] = rr; }
        }
    }
}

// degree histogram
__global__ void k_hist(int n) {
    int i = blockIdx.x * blockDim.x + threadIdx.x;
    if (i >= n) return;
    atomicAdd(&g_bkt[min(g_cnt[i], NBUCKET - 1)], 1);
}

// exclusive scan of 128 bucket counts (one block)
__global__ void k_bscan() {
    __shared__ int s[NBUCKET];
    int t = threadIdx.x;
    int v = g_bkt[t];
    s[t] = v;
    __syncthreads();
    for (int d = 1; d < NBUCKET; d <<= 1) {
        int u = (t >= d) ? s[t - d] : 0;
        __syncthreads();
        s[t] += u;
        __syncthreads();
    }
    g_bcur[t] = s[t] - v;   // exclusive prefix = initial cursor
}

// scatter node ids into degree-sorted permutation
__global__ void k_perm(int n) {
    int i = blockIdx.x * blockDim.x + threadIdx.x;
    if (i >= n) return;
    int p = atomicAdd(&g_bcur[min(g_cnt[i], NBUCKET - 1)], 1);
    g_perm[p] = i;
}

// ---------------- compute ----------------

// hs = fp16( dinv * (x @ W1) )
__global__ void k_mm1(const float* __restrict__ x, const float* __restrict__ W1, int n) {
    __shared__ float4 Ws[IN_CH * HID / 4];
    for (int t = threadIdx.x; t < IN_CH * HID / 4; t += blockDim.x)
        Ws[t] = ((const float4*)W1)[t];
    __syncthreads();

    int i = blockIdx.x * blockDim.x + threadIdx.x;
    if (i >= n) return;

    float a[HID];
#pragma unroll
    for (int j = 0; j < HID; j++) a[j] = 0.0f;

    const float4* xr = (const float4*)(x + (size_t)i * IN_CH);
#pragma unroll 8
    for (int k4 = 0; k4 < IN_CH / 4; k4++) {
        float4 xv = xr[k4];
        float xs[4] = {xv.x, xv.y, xv.z, xv.w};
#pragma unroll
        for (int r = 0; r < 4; r++) {
            const float4* w = &Ws[(k4 * 4 + r) * 4];
#pragma unroll
            for (int q = 0; q < 4; q++) {
                float4 wv = w[q];
                a[4 * q + 0] += xs[r] * wv.x;
                a[4 * q + 1] += xs[r] * wv.y;
                a[4 * q + 2] += xs[r] * wv.z;
                a[4 * q + 3] += xs[r] * wv.w;
            }
        }
    }

    float d = rsqrtf((float)(g_cnt[i] + 1));
    uint4 pack[2];
    __half2* hp = (__half2*)pack;
#pragma unroll
    for (int j = 0; j < 8; j++)
        hp[j] = __floats2half2_rn(d * a[2 * j], d * a[2 * j + 1]);
    ((uint4*)g_hs)[(size_t)i * 2 + 0] = pack[0];
    ((uint4*)g_hs)[(size_t)i * 2 + 1] = pack[1];
}

// accumulate one fp16x8 message into fp32 acc[8]
__device__ __forceinline__ void acc_msg(float* a, uint4 v) {
    const __half2* h = reinterpret_cast<const __half2*>(&v);
#pragma unroll
    for (int t = 0; t < 4; t++) {
        float2 f = __half22float2(h[t]);
        a[2 * t]     += f.x;
        a[2 * t + 1] += f.y;
    }
}

// gather a[8] over adjacency slots [k, end), k multiple of 4; 4-wide pipeline
__device__ __forceinline__ void seg_gather(const uint4* __restrict__ S,
                                           float* a, const int* __restrict__ adj,
                                           int k, int end, int pp) {
    const int4* adj4 = (const int4*)adj;   // adj row is 256B aligned; k % 4 == 0

    if (k + 4 <= end) {
        int4 ra = __ldg(&adj4[k >> 2]);
        k += 4;
        while (k + 4 <= end) {
            int4 nx = __ldg(&adj4[k >> 2]);
            uint4 v0 = S[(size_t)ra.x * 2 + pp];
            uint4 v1 = S[(size_t)ra.y * 2 + pp];
            uint4 v2 = S[(size_t)ra.z * 2 + pp];
            uint4 v3 = S[(size_t)ra.w * 2 + pp];
            acc_msg(a, v0); acc_msg(a, v1); acc_msg(a, v2); acc_msg(a, v3);
            ra = nx;
            k += 4;
        }
        uint4 v0 = S[(size_t)ra.x * 2 + pp];
        uint4 v1 = S[(size_t)ra.y * 2 + pp];
        uint4 v2 = S[(size_t)ra.z * 2 + pp];
        uint4 v3 = S[(size_t)ra.w * 2 + pp];
        acc_msg(a, v0); acc_msg(a, v1); acc_msg(a, v2); acc_msg(a, v3);
    }

    for (; k < end; k++) {
        uint4 v = S[(size_t)__ldg(&adj[k]) * 2 + pp];
        acc_msg(a, v);
    }
}

// exact overflow fixup (overflow list is ≈always empty)
__device__ __forceinline__ void ovf_fixup(const uint4* __restrict__ S,
                                          float* a, int i, int pp) {
    int no = min(g_ovf_cnt, OVF_MAX);
    for (int o = 0; o < no; o++) {
        if (g_ovf[2 * o] == i) {
            uint4 v = S[(size_t)g_ovf[2 * o + 1] * 2 + pp];
            acc_msg(a, v);
        }
    }
}

// 4-lane node gather front-end: pp = feature half, seg = edge-range half.
__device__ __forceinline__ void node_gather4(const uint4* __restrict__ S,
                                             float* a, int i, int cnt,
                                             int pp, int seg, unsigned qmask) {
#pragma unroll
    for (int j = 0; j < 8; j++) a[j] = 0.0f;

    int cn  = min(cnt, MAXD);
    int mid = min(cn, ((cn >> 1) + 3) & ~3);   // 4-aligned split point
    int k0  = seg ? mid : 0;
    int k1  = seg ? cn  : mid;

    if (seg == 0) acc_msg(a, S[(size_t)i * 2 + pp]);   // self-loop once
    seg_gather(S, a, &g_adj[(size_t)i << 6], k0, k1, pp);
    if (seg == 1 && cnt > MAXD) ovf_fixup(S, a, i, pp);

    // allreduce across the two segments (xor 2 flips seg, keeps pp)
#pragma unroll
    for (int j = 0; j < 8; j++)
        a[j] += __shfl_xor_sync(qmask, a[j], 2, 4);
}

// gather layer-1 + fused: h1 = relu(d*a + b1); hs2 = fp16(d*(h1 @ W2))
__global__ void __launch_bounds__(256, 8)
k_gather_mid(const float* __restrict__ W2, const float* __restrict__ b1, int n) {
    __shared__ float Ws[HID * HID];
    if (threadIdx.x < HID * HID / 4)
        ((float4*)Ws)[threadIdx.x] = ((const float4*)W2)[threadIdx.x];
    __syncthreads();

    int gid = blockIdx.x * blockDim.x + threadIdx.x;
    int ni  = gid >> 2;
    int pp  = gid & 1;
    int seg = (gid >> 1) & 1;
    if (ni >= n) return;
    int i = __ldg(&g_perm[ni]);          // degree-sorted order: uniform warp work

    unsigned lane = threadIdx.x & 31u;
    unsigned qmask = 0xFu << (lane & ~3u);

    const uint4* S = (const uint4*)g_hs;
    float a[8];
    int cnt = g_cnt[i];
    node_gather4(S, a, i, cnt, pp, seg, qmask);

    float d = rsqrtf((float)(cnt + 1));
    float h8[8];
    const float* bb = b1 + pp * 8;
#pragma unroll
    for (int j = 0; j < 8; j++)
        h8[j] = fmaxf(d * a[j] + __ldg(&bb[j]), 0.0f);

    // exchange halves across pp (xor 1 flips pp, keeps seg)
    float hall[HID];
#pragma unroll
    for (int j = 0; j < 8; j++) hall[pp * 8 + j] = h8[j];
#pragma unroll
    for (int j = 0; j < 8; j++)
        hall[(pp ^ 1) * 8 + j] = __shfl_xor_sync(qmask, h8[j], 1, 4);

    float t[8];
#pragma unroll
    for (int j = 0; j < 8; j++) t[j] = 0.0f;
#pragma unroll
    for (int k = 0; k < HID; k++) {
        float hk = hall[k];
        const float* w = &Ws[k * HID + pp * 8];
#pragma unroll
        for (int j = 0; j < 8; j++) t[j] += hk * w[j];
    }

    if (seg == 0) {
        uint4 pack;
        __half2* hp = (__half2*)&pack;
#pragma unroll
        for (int j = 0; j < 4; j++)
            hp[j] = __floats2half2_rn(d * t[2 * j], d * t[2 * j + 1]);
        ((uint4*)g_hs2)[(size_t)i * 2 + pp] = pack;
    }
}

// gather layer-2 + fused readout: out = relu(d*a + b2) . Wl + bl
__global__ void __launch_bounds__(256, 8)
k_gather_final(const float* __restrict__ b2, const float* __restrict__ Wl,
               const float* __restrict__ bl, float* __restrict__ out, int n) {
    int gid = blockIdx.x * blockDim.x + threadIdx.x;
    int ni  = gid >> 2;
    int pp  = gid & 1;
    int seg = (gid >> 1) & 1;
    if (ni >= n) return;
    int i = __ldg(&g_perm[ni]);

    unsigned lane = threadIdx.x & 31u;
    unsigned qmask = 0xFu << (lane & ~3u);

    const uint4* S = (const uint4*)g_hs2;
    float a[8];
    int cnt = g_cnt[i];
    node_gather4(S, a, i, cnt, pp, seg, qmask);

    float d = rsqrtf((float)(cnt + 1));
    const float* bb = b2 + pp * 8;
    const float* ww = Wl + pp * 8;
    float s = 0.0f;
#pragma unroll
    for (int j = 0; j < 8; j++)
        s += fmaxf(d * a[j] + __ldg(&bb[j]), 0.0f) * __ldg(&ww[j]);

    // reduce across pp (xor 1); lane (pp==0,seg==0) writes
    s += __shfl_xor_sync(qmask, s, 1, 4);
    if (pp == 0 && seg == 0) out[i] = s + __ldg(bl);
}

// ---------------- launch ----------------

extern "C" void kernel_launch(void* const* d_in, const int* in_sizes, int n_in,
                              void* d_out, int out_size) {
    const float* x   = (const float*)d_in[0];
    const int*   ei  = (const int*)  d_in[1];
    const float* W1  = (const float*)d_in[2];
    const float* b1  = (const float*)d_in[3];
    const float* W2  = (const float*)d_in[4];
    const float* b2  = (const float*)d_in[5];
    const float* Wl  = (const float*)d_in[6];
    const float* bl  = (const float*)d_in[7];
    float* out = (float*)d_out;

    const int n = in_sizes[0] / IN_CH;   // 100000
    const int e = in_sizes[1] / 2;       // 3200000
    const int* row = ei;
    const int* col = ei + e;

    const int TB = 256;
    const int gn = (n + TB - 1) / TB;
    const int n4 = n / 4;
    const int e4 = e / 4;
    const int gq = (n * 4 + TB - 1) / TB;

    // build (single pass) + degree-bucketed permutation
    k_zero <<<(n4 + TB - 1) / TB, TB>>>(n4);
    k_build<<<(e4 + TB - 1) / TB, TB>>>(row, col, e4);
    k_hist <<<gn, TB>>>(n);
    k_bscan<<<1, NBUCKET>>>();
    k_perm <<<gn, TB>>>(n);

    // layer 1 (+ fused layer-2 transform)
    k_mm1       <<<gn, TB>>>(x, W1, n);
    k_gather_mid<<<gq, TB>>>(W2, b1, n);

    // layer 2 (+ fused readout)
    k_gather_final<<<gq, TB>>>(b2, Wl, bl, out, n);
}

// round 15
// speedup vs baseline: 1.2884x; 1.2884x over previous
#include <cuda_runtime.h>
#include <cuda_fp16.h>
#include <cuda_bf16.h>

#define N_NODES 100000
#define N_EDGES 3200000
#define IN_CH   128
#define HID     16
#define MAXD    64            // fixed adjacency stride; overflow handled exactly
#define OVF_MAX 4096
#define WIN     1024          // locality window for degree sorting
#define WBUCK   64            // degree buckets within a window

// ---------------- device scratch (no allocation allowed) ----------------
__device__ __align__(16) int    g_cnt[N_NODES];
__device__ __align__(16) int    g_adj[N_NODES * MAXD];   // 25.6 MB fixed-stride adjacency
__device__ int                  g_ovf_cnt;
__device__ __align__(16) int    g_ovf[2 * OVF_MAX];      // (col,row) overflow pairs
__device__ __align__(16) int    g_perm[N_NODES];         // window-local degree-sorted order
__device__ __align__(16) __half g_hs [N_NODES * HID];    // layer-1 messages (fp16)
__device__ __align__(16) __half g_hs2[N_NODES * HID];    // layer-2 messages (fp16)

__device__ __forceinline__ unsigned h2u(__half2 h) {
    return *reinterpret_cast<unsigned*>(&h);
}

// ---------------- build ----------------

__global__ void k_zero(int n4) {
    int i = blockIdx.x * blockDim.x + threadIdx.x;
    if (i < n4) ((int4*)g_cnt)[i] = make_int4(0, 0, 0, 0);
    if (i == 0) g_ovf_cnt = 0;
}

// single-pass adjacency build; atomic return value doubles as degree histogram
__global__ void k_build(const int* __restrict__ row, const int* __restrict__ col, int e4) {
    int i = blockIdx.x * blockDim.x + threadIdx.x;
    if (i >= e4) return;
    int4 r = __ldg(&((const int4*)row)[i]);
    int4 c = __ldg(&((const int4*)col)[i]);
#pragma unroll
    for (int u = 0; u < 4; u++) {
        int cc = (u == 0) ? c.x : (u == 1) ? c.y : (u == 2) ? c.z : c.w;
        int rr = (u == 0) ? r.x : (u == 1) ? r.y : (u == 2) ? r.z : r.w;
        int p = atomicAdd(&g_cnt[cc], 1);
        if (p < MAXD) {
            g_adj[(cc << 6) + p] = rr;
        } else {
            int o = atomicAdd(&g_ovf_cnt, 1);
            if (o < OVF_MAX) { g_ovf[2 * o] = cc; g_ovf[2 * o + 1] = rr; }
        }
    }
}

// window-local counting sort by degree: one block per 1024-node window.
// Preserves locality (perm[i] stays within the window) while making warp
// neighborhoods degree-uniform.
__global__ void k_wsort(int n) {
    __shared__ int hist[WBUCK];
    __shared__ int cur [WBUCK];
    int base = blockIdx.x * WIN;
    int w    = min(WIN, n - base);
    if (w <= 0) return;

    if (threadIdx.x < WBUCK) hist[threadIdx.x] = 0;
    __syncthreads();

    // histogram (4 nodes per thread)
#pragma unroll
    for (int u = 0; u < WIN / 256; u++) {
        int t = threadIdx.x * (WIN / 256) + u;
        if (t < w) atomicAdd(&hist[min(g_cnt[base + t], WBUCK - 1)], 1);
    }
    __syncthreads();

    // exclusive scan of 64 buckets in two warps -> serial in warp 0 (tiny)
    if (threadIdx.x == 0) {
        int run = 0;
        for (int b = 0; b < WBUCK; b++) { cur[b] = run; run += hist[b]; }
    }
    __syncthreads();

    // scatter node ids (ascending degree within the window)
#pragma unroll
    for (int u = 0; u < WIN / 256; u++) {
        int t = threadIdx.x * (WIN / 256) + u;
        if (t < w) {
            int b = min(g_cnt[base + t], WBUCK - 1);
            int p = atomicAdd(&cur[b], 1);
            g_perm[base + p] = base + t;
        }
    }
}

// ---------------- compute ----------------

// hs = fp16( dinv * (x @ W1) )
__global__ void k_mm1(const float* __restrict__ x, const float* __restrict__ W1, int n) {
    __shared__ float4 Ws[IN_CH * HID / 4];
    for (int t = threadIdx.x; t < IN_CH * HID / 4; t += blockDim.x)
        Ws[t] = ((const float4*)W1)[t];
    __syncthreads();

    int i = blockIdx.x * blockDim.x + threadIdx.x;
    if (i >= n) return;

    float a[HID];
#pragma unroll
    for (int j = 0; j < HID; j++) a[j] = 0.0f;

    const float4* xr = (const float4*)(x + (size_t)i * IN_CH);
#pragma unroll 8
    for (int k4 = 0; k4 < IN_CH / 4; k4++) {
        float4 xv = xr[k4];
        float xs[4] = {xv.x, xv.y, xv.z, xv.w};
#pragma unroll
        for (int r = 0; r < 4; r++) {
            const float4* w = &Ws[(k4 * 4 + r) * 4];
#pragma unroll
            for (int q = 0; q < 4; q++) {
                float4 wv = w[q];
                a[4 * q + 0] += xs[r] * wv.x;
                a[4 * q + 1] += xs[r] * wv.y;
                a[4 * q + 2] += xs[r] * wv.z;
                a[4 * q + 3] += xs[r] * wv.w;
            }
        }
    }

    float d = rsqrtf((float)(g_cnt[i] + 1));
    uint4 pack[2];
    __half2* hp = (__half2*)pack;
#pragma unroll
    for (int j = 0; j < 8; j++)
        hp[j] = __floats2half2_rn(d * a[2 * j], d * a[2 * j + 1]);
    ((uint4*)g_hs)[(size_t)i * 2 + 0] = pack[0];
    ((uint4*)g_hs)[(size_t)i * 2 + 1] = pack[1];
}

// accumulate one fp16x8 message into fp32 acc[8]
__device__ __forceinline__ void acc_msg(float* a, uint4 v) {
    const __half2* h = reinterpret_cast<const __half2*>(&v);
#pragma unroll
    for (int t = 0; t < 4; t++) {
        float2 f = __half22float2(h[t]);
        a[2 * t]     += f.x;
        a[2 * t + 1] += f.y;
    }
}

// gather a[8] over adjacency slots [k, end), k multiple of 4; 4-wide pipeline
__device__ __forceinline__ void seg_gather(const uint4* __restrict__ S,
                                           float* a, const int* __restrict__ adj,
                                           int k, int end, int pp) {
    const int4* adj4 = (const int4*)adj;   // adj row is 256B aligned; k % 4 == 0

    if (k + 4 <= end) {
        int4 ra = __ldg(&adj4[k >> 2]);
        k += 4;
        while (k + 4 <= end) {
            int4 nx = __ldg(&adj4[k >> 2]);
            uint4 v0 = S[(size_t)ra.x * 2 + pp];
            uint4 v1 = S[(size_t)ra.y * 2 + pp];
            uint4 v2 = S[(size_t)ra.z * 2 + pp];
            uint4 v3 = S[(size_t)ra.w * 2 + pp];
            acc_msg(a, v0); acc_msg(a, v1); acc_msg(a, v2); acc_msg(a, v3);
            ra = nx;
            k += 4;
        }
        uint4 v0 = S[(size_t)ra.x * 2 + pp];
        uint4 v1 = S[(size_t)ra.y * 2 + pp];
        uint4 v2 = S[(size_t)ra.z * 2 + pp];
        uint4 v3 = S[(size_t)ra.w * 2 + pp];
        acc_msg(a, v0); acc_msg(a, v1); acc_msg(a, v2); acc_msg(a, v3);
    }

    for (; k < end; k++) {
        uint4 v = S[(size_t)__ldg(&adj[k]) * 2 + pp];
        acc_msg(a, v);
    }
}

// exact overflow fixup (overflow list is ≈always empty)
__device__ __forceinline__ void ovf_fixup(const uint4* __restrict__ S,
                                          float* a, int i, int pp) {
    int no = min(g_ovf_cnt, OVF_MAX);
    for (int o = 0; o < no; o++) {
        if (g_ovf[2 * o] == i) {
            uint4 v = S[(size_t)g_ovf[2 * o + 1] * 2 + pp];
            acc_msg(a, v);
        }
    }
}

// 4-lane node gather front-end: pp = feature half, seg = edge-range half.
__device__ __forceinline__ void node_gather4(const uint4* __restrict__ S,
                                             float* a, int i, int cnt,
                                             int pp, int seg, unsigned qmask) {
#pragma unroll
    for (int j = 0; j < 8; j++) a[j] = 0.0f;

    int cn  = min(cnt, MAXD);
    int mid = min(cn, ((cn >> 1) + 3) & ~3);   // 4-aligned split point
    int k0  = seg ? mid : 0;
    int k1  = seg ? cn  : mid;

    if (seg == 0) acc_msg(a, S[(size_t)i * 2 + pp]);   // self-loop once
    seg_gather(S, a, &g_adj[(size_t)i << 6], k0, k1, pp);
    if (seg == 1 && cnt > MAXD) ovf_fixup(S, a, i, pp);

    // allreduce across the two segments (xor 2 flips seg, keeps pp)
#pragma unroll
    for (int j = 0; j < 8; j++)
        a[j] += __shfl_xor_sync(qmask, a[j], 2, 4);
}

// gather layer-1 + fused: h1 = relu(d*a + b1); hs2 = fp16(d*(h1 @ W2))
__global__ void __launch_bounds__(256, 8)
k_gather_mid(const float* __restrict__ W2, const float* __restrict__ b1, int n) {
    __shared__ float Ws[HID * HID];
    if (threadIdx.x < HID * HID / 4)
        ((float4*)Ws)[threadIdx.x] = ((const float4*)W2)[threadIdx.x];
    __syncthreads();

    int gid = blockIdx.x * blockDim.x + threadIdx.x;
    int ni  = gid >> 2;
    int pp  = gid & 1;
    int seg = (gid >> 1) & 1;
    if (ni >= n) return;
    int i = __ldg(&g_perm[ni]);          // window-local degree order

    unsigned lane = threadIdx.x & 31u;
    unsigned qmask = 0xFu << (lane & ~3u);

    const uint4* S = (const uint4*)g_hs;
    float a[8];
    int cnt = g_cnt[i];
    node_gather4(S, a, i, cnt, pp, seg, qmask);

    float d = rsqrtf((float)(cnt + 1));
    float h8[8];
    const float* bb = b1 + pp * 8;
#pragma unroll
    for (int j = 0; j < 8; j++)
        h8[j] = fmaxf(d * a[j] + __ldg(&bb[j]), 0.0f);

    // exchange halves across pp (xor 1 flips pp, keeps seg)
    float hall[HID];
#pragma unroll
    for (int j = 0; j < 8; j++) hall[pp * 8 + j] = h8[j];
#pragma unroll
    for (int j = 0; j < 8; j++)
        hall[(pp ^ 1) * 8 + j] = __shfl_xor_sync(qmask, h8[j], 1, 4);

    float t[8];
#pragma unroll
    for (int j = 0; j < 8; j++) t[j] = 0.0f;
#pragma unroll
    for (int k = 0; k < HID; k++) {
        float hk = hall[k];
        const float* w = &Ws[k * HID + pp * 8];
#pragma unroll
        for (int j = 0; j < 8; j++) t[j] += hk * w[j];
    }

    if (seg == 0) {
        uint4 pack;
        __half2* hp = (__half2*)&pack;
#pragma unroll
        for (int j = 0; j < 4; j++)
            hp[j] = __floats2half2_rn(d * t[2 * j], d * t[2 * j + 1]);
        ((uint4*)g_hs2)[(size_t)i * 2 + pp] = pack;
    }
}

// gather layer-2 + fused readout: out = relu(d*a + b2) . Wl + bl
__global__ void __launch_bounds__(256, 8)
k_gather_final(const float* __restrict__ b2, const float* __restrict__ Wl,
               const float* __restrict__ bl, float* __restrict__ out, int n) {
    int gid = blockIdx.x * blockDim.x + threadIdx.x;
    int ni  = gid >> 2;
    int pp  = gid & 1;
    int seg = (gid >> 1) & 1;
    if (ni >= n) return;
    int i = __ldg(&g_perm[ni]);

    unsigned lane = threadIdx.x & 31u;
    unsigned qmask = 0xFu << (lane & ~3u);

    const uint4* S = (const uint4*)g_hs2;
    float a[8];
    int cnt = g_cnt[i];
    node_gather4(S, a, i, cnt, pp, seg, qmask);

    float d = rsqrtf((float)(cnt + 1));
    const float* bb = b2 + pp * 8;
    const float* ww = Wl + pp * 8;
    float s = 0.0f;
#pragma unroll
    for (int j = 0; j < 8; j++)
        s += fmaxf(d * a[j] + __ldg(&bb[j]), 0.0f) * __ldg(&ww[j]);

    // reduce across pp (xor 1); lane (pp==0,seg==0) writes
    s += __shfl_xor_sync(qmask, s, 1, 4);
    if (pp == 0 && seg == 0) out[i] = s + __ldg(bl);
}

// ---------------- launch ----------------

extern "C" void kernel_launch(void* const* d_in, const int* in_sizes, int n_in,
                              void* d_out, int out_size) {
    const float* x   = (const float*)d_in[0];
    const int*   ei  = (const int*)  d_in[1];
    const float* W1  = (const float*)d_in[2];
    const float* b1  = (const float*)d_in[3];
    const float* W2  = (const float*)d_in[4];
    const float* b2  = (const float*)d_in[5];
    const float* Wl  = (const float*)d_in[6];
    const float* bl  = (const float*)d_in[7];
    float* out = (float*)d_out;

    const int n = in_sizes[0] / IN_CH;   // 100000
    const int e = in_sizes[1] / 2;       // 3200000
    const int* row = ei;
    const int* col = ei + e;

    const int TB = 256;
    const int gn = (n + TB - 1) / TB;
    const int n4 = n / 4;
    const int e4 = e / 4;
    const int gq = (n * 4 + TB - 1) / TB;
    const int nw = (n + WIN - 1) / WIN;

    // build (single pass) + window-local degree sort
    k_zero <<<(n4 + TB - 1) / TB, TB>>>(n4);
    k_build<<<(e4 + TB - 1) / TB, TB>>>(row, col, e4);
    k_wsort<<<nw, TB>>>(n);

    // layer 1 (+ fused layer-2 transform)
    k_mm1       <<<gn, TB>>>(x, W1, n);
    k_gather_mid<<<gq, TB>>>(W2, b1, n);

    // layer 2 (+ fused readout)
    k_gather_final<<<gq, TB>>>(b2, Wl, bl, out, n);
}

// round 16
// speedup vs baseline: 1.4271x; 1.1077x over previous
#include <cuda_runtime.h>
#include <cuda_fp16.h>
#include <cuda_bf16.h>

#define N_NODES 100000
#define N_EDGES 3200000
#define IN_CH   128
#define HID     16
#define MAXD    64            // fixed adjacency stride; overflow handled exactly
#define OVF_MAX 4096

// ---------------- device scratch (no allocation allowed) ----------------
__device__ __align__(16) int    g_cnt[N_NODES];
__device__ __align__(16) int    g_adj[N_NODES * MAXD];   // 25.6 MB fixed-stride adjacency
__device__ int                  g_ovf_cnt;
__device__ __align__(16) int    g_ovf[2 * OVF_MAX];      // (col,row) overflow pairs
__device__ __align__(16) __half g_hs [N_NODES * HID];    // layer-1 messages (fp16)
__device__ __align__(16) __half g_hs2[N_NODES * HID];    // layer-2 messages (fp16)

__device__ __forceinline__ unsigned h2u(__half2 h) {
    return *reinterpret_cast<unsigned*>(&h);
}

// ---------------- build ----------------

__global__ void k_zero(int n4) {
    int i = blockIdx.x * blockDim.x + threadIdx.x;
    if (i < n4) ((int4*)g_cnt)[i] = make_int4(0, 0, 0, 0);
    if (i == 0) g_ovf_cnt = 0;
}

// single-pass adjacency build; atomic return value doubles as degree histogram
__global__ void k_build(const int* __restrict__ row, const int* __restrict__ col, int e4) {
    int i = blockIdx.x * blockDim.x + threadIdx.x;
    if (i >= e4) return;
    int4 r = __ldg(&((const int4*)row)[i]);
    int4 c = __ldg(&((const int4*)col)[i]);
#pragma unroll
    for (int u = 0; u < 4; u++) {
        int cc = (u == 0) ? c.x : (u == 1) ? c.y : (u == 2) ? c.z : c.w;
        int rr = (u == 0) ? r.x : (u == 1) ? r.y : (u == 2) ? r.z : r.w;
        int p = atomicAdd(&g_cnt[cc], 1);
        if (p < MAXD) {
            g_adj[(cc << 6) + p] = rr;
        } else {
            int o = atomicAdd(&g_ovf_cnt, 1);
            if (o < OVF_MAX) { g_ovf[2 * o] = cc; g_ovf[2 * o + 1] = rr; }
        }
    }
}

// ---------------- compute ----------------

// hs = fp16( dinv * (x @ W1) ), smem-staged coalesced x reads.
// Block = 256 nodes; 4 k-chunks of 32 floats; sx padded to 36 floats/row.
__global__ void k_mm1(const float* __restrict__ x, const float* __restrict__ W1, int n) {
    __shared__ float4 Ws[IN_CH * HID / 4];   // 8 KB: W1[k][j] as float4 over j
    __shared__ float  sx[256 * 36];          // 36 KB staged x chunk (padded rows)

    for (int t = threadIdx.x; t < IN_CH * HID / 4; t += blockDim.x)
        Ws[t] = ((const float4*)W1)[t];

    int base = blockIdx.x * 256;
    int tid  = threadIdx.x;
    const float4* x4 = (const float4*)x;

    float a[HID];
#pragma unroll
    for (int j = 0; j < HID; j++) a[j] = 0.0f;

#pragma unroll
    for (int kc = 0; kc < 4; kc++) {
        __syncthreads();   // protect sx from previous chunk's readers (and Ws on kc=0)
        // cooperative coalesced load: 2048 float4s, consecutive lanes -> consecutive f4
#pragma unroll
        for (int u = 0; u < 8; u++) {
            int j    = u * 256 + tid;
            int node = j >> 3;       // 0..255
            int off  = j & 7;        // 0..7 (float4 within 32-float chunk)
            float4 v = make_float4(0.f, 0.f, 0.f, 0.f);
            if (base + node < n)
                v = x4[(size_t)(base + node) * 32 + kc * 8 + off];
            *(float4*)&sx[node * 36 + off * 4] = v;
        }
        __syncthreads();

        if (base + tid < n) {
#pragma unroll
            for (int off = 0; off < 8; off++) {
                float4 xv = *(float4*)&sx[tid * 36 + off * 4];
                float xs[4] = {xv.x, xv.y, xv.z, xv.w};
#pragma unroll
                for (int r = 0; r < 4; r++) {
                    int kk = kc * 32 + off * 4 + r;
                    const float4* w = &Ws[kk * 4];
#pragma unroll
                    for (int q = 0; q < 4; q++) {
                        float4 wv = w[q];
                        a[4 * q + 0] += xs[r] * wv.x;
                        a[4 * q + 1] += xs[r] * wv.y;
                        a[4 * q + 2] += xs[r] * wv.z;
                        a[4 * q + 3] += xs[r] * wv.w;
                    }
                }
            }
        }
    }

    int i = base + tid;
    if (i >= n) return;

    float d = rsqrtf((float)(g_cnt[i] + 1));
    uint4 pack[2];
    __half2* hp = (__half2*)pack;
#pragma unroll
    for (int j = 0; j < 8; j++)
        hp[j] = __floats2half2_rn(d * a[2 * j], d * a[2 * j + 1]);
    ((uint4*)g_hs)[(size_t)i * 2 + 0] = pack[0];
    ((uint4*)g_hs)[(size_t)i * 2 + 1] = pack[1];
}

// accumulate one fp16x8 message into fp32 acc[8]
__device__ __forceinline__ void acc_msg(float* a, uint4 v) {
    const __half2* h = reinterpret_cast<const __half2*>(&v);
#pragma unroll
    for (int t = 0; t < 4; t++) {
        float2 f = __half22float2(h[t]);
        a[2 * t]     += f.x;
        a[2 * t + 1] += f.y;
    }
}

// gather a[8] over adjacency slots [k, end), k multiple of 4; int4 index loads
__device__ __forceinline__ void seg_gather(const uint4* __restrict__ S,
                                           float* a, const int* __restrict__ adj,
                                           int k, int end, int pp) {
    const int4* adj4 = (const int4*)adj;   // adj row is 256B aligned; k % 4 == 0

    if (k + 8 <= end) {
        int4 ra = __ldg(&adj4[k >> 2]);
        int4 rb = __ldg(&adj4[(k >> 2) + 1]);
        k += 8;
        while (k + 8 <= end) {
            int4 na = __ldg(&adj4[k >> 2]);
            int4 nb = __ldg(&adj4[(k >> 2) + 1]);
            uint4 v[8];
            v[0] = S[(size_t)ra.x * 2 + pp];
            v[1] = S[(size_t)ra.y * 2 + pp];
            v[2] = S[(size_t)ra.z * 2 + pp];
            v[3] = S[(size_t)ra.w * 2 + pp];
            v[4] = S[(size_t)rb.x * 2 + pp];
            v[5] = S[(size_t)rb.y * 2 + pp];
            v[6] = S[(size_t)rb.z * 2 + pp];
            v[7] = S[(size_t)rb.w * 2 + pp];
#pragma unroll
            for (int u = 0; u < 8; u++) acc_msg(a, v[u]);
            ra = na; rb = nb;
            k += 8;
        }
        uint4 v[8];
        v[0] = S[(size_t)ra.x * 2 + pp];
        v[1] = S[(size_t)ra.y * 2 + pp];
        v[2] = S[(size_t)ra.z * 2 + pp];
        v[3] = S[(size_t)ra.w * 2 + pp];
        v[4] = S[(size_t)rb.x * 2 + pp];
        v[5] = S[(size_t)rb.y * 2 + pp];
        v[6] = S[(size_t)rb.z * 2 + pp];
        v[7] = S[(size_t)rb.w * 2 + pp];
#pragma unroll
        for (int u = 0; u < 8; u++) acc_msg(a, v[u]);
    }

    if (k + 4 <= end) {
        int4 ra = __ldg(&adj4[k >> 2]);
        uint4 v0 = S[(size_t)ra.x * 2 + pp];
        uint4 v1 = S[(size_t)ra.y * 2 + pp];
        uint4 v2 = S[(size_t)ra.z * 2 + pp];
        uint4 v3 = S[(size_t)ra.w * 2 + pp];
        acc_msg(a, v0); acc_msg(a, v1); acc_msg(a, v2); acc_msg(a, v3);
        k += 4;
    }

    for (; k < end; k++) {
        uint4 v = S[(size_t)__ldg(&adj[k]) * 2 + pp];
        acc_msg(a, v);
    }
}

// exact overflow fixup (overflow list is ≈always empty)
__device__ __forceinline__ void ovf_fixup(const uint4* __restrict__ S,
                                          float* a, int i, int pp) {
    int no = min(g_ovf_cnt, OVF_MAX);
    for (int o = 0; o < no; o++) {
        if (g_ovf[2 * o] == i) {
            uint4 v = S[(size_t)g_ovf[2 * o + 1] * 2 + pp];
            acc_msg(a, v);
        }
    }
}

// 4-lane node gather front-end: pp = feature half, seg = edge-range half.
__device__ __forceinline__ void node_gather4(const uint4* __restrict__ S,
                                             float* a, int i, int cnt,
                                             int pp, int seg, unsigned qmask) {
#pragma unroll
    for (int j = 0; j < 8; j++) a[j] = 0.0f;

    int cn  = min(cnt, MAXD);
    int mid = min(cn, ((cn >> 1) + 3) & ~3);   // 4-aligned split point
    int k0  = seg ? mid : 0;
    int k1  = seg ? cn  : mid;

    if (seg == 0) acc_msg(a, S[(size_t)i * 2 + pp]);   // self-loop once
    seg_gather(S, a, &g_adj[(size_t)i << 6], k0, k1, pp);
    if (seg == 1 && cnt > MAXD) ovf_fixup(S, a, i, pp);

    // allreduce across the two segments (xor 2 flips seg, keeps pp)
#pragma unroll
    for (int j = 0; j < 8; j++)
        a[j] += __shfl_xor_sync(qmask, a[j], 2, 4);
}

// gather layer-1 + fused: h1 = relu(d*a + b1); hs2 = fp16(d*(h1 @ W2))
__global__ void k_gather_mid(const float* __restrict__ W2, const float* __restrict__ b1, int n) {
    __shared__ float Ws[HID * HID];
    if (threadIdx.x < HID * HID / 4)
        ((float4*)Ws)[threadIdx.x] = ((const float4*)W2)[threadIdx.x];
    __syncthreads();

    int gid = blockIdx.x * blockDim.x + threadIdx.x;
    int i   = gid >> 2;
    int pp  = gid & 1;
    int seg = (gid >> 1) & 1;
    if (i >= n) return;

    unsigned lane = threadIdx.x & 31u;
    unsigned qmask = 0xFu << (lane & ~3u);

    const uint4* S = (const uint4*)g_hs;
    float a[8];
    int cnt = g_cnt[i];
    node_gather4(S, a, i, cnt, pp, seg, qmask);

    float d = rsqrtf((float)(cnt + 1));
    float h8[8];
    const float* bb = b1 + pp * 8;
#pragma unroll
    for (int j = 0; j < 8; j++)
        h8[j] = fmaxf(d * a[j] + __ldg(&bb[j]), 0.0f);

    // exchange halves across pp (xor 1 flips pp, keeps seg)
    float hall[HID];
#pragma unroll
    for (int j = 0; j < 8; j++) hall[pp * 8 + j] = h8[j];
#pragma unroll
    for (int j = 0; j < 8; j++)
        hall[(pp ^ 1) * 8 + j] = __shfl_xor_sync(qmask, h8[j], 1, 4);

    float t[8];
#pragma unroll
    for (int j = 0; j < 8; j++) t[j] = 0.0f;
#pragma unroll
    for (int k = 0; k < HID; k++) {
        float hk = hall[k];
        const float* w = &Ws[k * HID + pp * 8];
#pragma unroll
        for (int j = 0; j < 8; j++) t[j] += hk * w[j];
    }

    if (seg == 0) {
        uint4 pack;
        __half2* hp = (__half2*)&pack;
#pragma unroll
        for (int j = 0; j < 4; j++)
            hp[j] = __floats2half2_rn(d * t[2 * j], d * t[2 * j + 1]);
        ((uint4*)g_hs2)[(size_t)i * 2 + pp] = pack;
    }
}

// gather layer-2 + fused readout: out = relu(d*a + b2) . Wl + bl
__global__ void k_gather_final(const float* __restrict__ b2, const float* __restrict__ Wl,
                               const float* __restrict__ bl, float* __restrict__ out, int n) {
    int gid = blockIdx.x * blockDim.x + threadIdx.x;
    int i   = gid >> 2;
    int pp  = gid & 1;
    int seg = (gid >> 1) & 1;
    if (i >= n) return;

    unsigned lane = threadIdx.x & 31u;
    unsigned qmask = 0xFu << (lane & ~3u);

    const uint4* S = (const uint4*)g_hs2;
    float a[8];
    int cnt = g_cnt[i];
    node_gather4(S, a, i, cnt, pp, seg, qmask);

    float d = rsqrtf((float)(cnt + 1));
    const float* bb = b2 + pp * 8;
    const float* ww = Wl + pp * 8;
    float s = 0.0f;
#pragma unroll
    for (int j = 0; j < 8; j++)
        s += fmaxf(d * a[j] + __ldg(&bb[j]), 0.0f) * __ldg(&ww[j]);

    // reduce across pp (xor 1); lane (pp==0,seg==0) writes
    s += __shfl_xor_sync(qmask, s, 1, 4);
    if (pp == 0 && seg == 0) out[i] = s + __ldg(bl);
}

// ---------------- launch ----------------

extern "C" void kernel_launch(void* const* d_in, const int* in_sizes, int n_in,
                              void* d_out, int out_size) {
    const float* x   = (const float*)d_in[0];
    const int*   ei  = (const int*)  d_in[1];
    const float* W1  = (const float*)d_in[2];
    const float* b1  = (const float*)d_in[3];
    const float* W2  = (const float*)d_in[4];
    const float* b2  = (const float*)d_in[5];
    const float* Wl  = (const float*)d_in[6];
    const float* bl  = (const float*)d_in[7];
    float* out = (float*)d_out;

    const int n = in_sizes[0] / IN_CH;   // 100000
    const int e = in_sizes[1] / 2;       // 3200000
    const int* row = ei;
    const int* col = ei + e;

    const int TB = 256;
    const int gn = (n + TB - 1) / TB;
    const int n4 = n / 4;
    const int e4 = e / 4;
    const int gq = (n * 4 + TB - 1) / TB;

    // build (single pass)
    k_zero <<<(n4 + TB - 1) / TB, TB>>>(n4);
    k_build<<<(e4 + TB - 1) / TB, TB>>>(row, col, e4);

    // layer 1 (+ fused layer-2 transform)
    k_mm1       <<<gn, TB>>>(x, W1, n);
    k_gather_mid<<<gq, TB>>>(W2, b1, n);

    // layer 2 (+ fused readout)
    k_gather_final<<<gq, TB>>>(b2, Wl, bl, out, n);
}